// round 6
// baseline (speedup 1.0000x reference)
#include <cuda_runtime.h>
#include <cuda_fp16.h>
#include <cstdint>

#define TT 16384
#define DD 2048
#define EE 64
#define BM 128
#define NT 512
#define NCH 32                 // K=32 chunks per K-half (each half = 1024)

// ---- epilogue smem (u32 offsets) ----
#define SC_STRIDE 66
#define BOARD_U32 (BM * SC_STRIDE)            // 8448
#define CNT (2 * BOARD_U32)
#define I1A (CNT + 64)
#define I2A (I1A + 128)
#define G1A (I2A + 128)
#define G2A (G1A + 128)
#define SMEM_U32 (G2A + 128)
#define SMEM_BYTES (SMEM_U32 * 4)             // ~70 KB

// ---- output layout (floats) ----
#define IDX_OFF  ((size_t)TT * EE)
#define GATE_OFF (IDX_OFF + 2 * (size_t)TT)
#define ACT_OFF  (GATE_OFF + 2 * (size_t)TT)
#define FULL_OUT (ACT_OFF + EE)

// w pre-split to fp16 hi/lo, fragment-major: [k16-step 128][nb 8][lane 32] uint4
// v = {b0_hi, b1_hi, b0_lo, b1_lo} for mma.m16n8k16 B fragment
__device__ uint4 g_w_frag[128 * 8 * 32];

__device__ __forceinline__ uint32_t packh2(__half a, __half b) {
    uint32_t u;
    asm("mov.b32 %0, {%1, %2};" : "=r"(u) : "h"(__half_as_ushort(a)), "h"(__half_as_ushort(b)));
    return u;
}
__device__ __forceinline__ void split_f16(float x, __half& h, __half& l) {
    h = __float2half_rn(x);
    l = __float2half_rn(x - __half2float(h));
}
// split a float2 into packed hi pair and lo pair
__device__ __forceinline__ uint32_t split2(float2 v, uint32_t& lo) {
    __half hx, lx, hy, ly;
    split_f16(v.x, hx, lx);
    split_f16(v.y, hy, ly);
    lo = packh2(lx, ly);
    return packh2(hx, hy);
}
__device__ __forceinline__ void mma_f16(float* d, const uint32_t* a, uint32_t b0, uint32_t b1) {
    asm volatile(
        "mma.sync.aligned.m16n8k16.row.col.f32.f16.f16.f32 "
        "{%0,%1,%2,%3}, {%4,%5,%6,%7}, {%8,%9}, {%0,%1,%2,%3};"
        : "+f"(d[0]), "+f"(d[1]), "+f"(d[2]), "+f"(d[3])
        : "r"(a[0]), "r"(a[1]), "r"(a[2]), "r"(a[3]), "r"(b0), "r"(b1));
}

// ======================= prep: w -> fragment-major fp16 hi/lo =======================
__global__ void prep_kernel(const float* __restrict__ w, float* __restrict__ out, int we) {
    int t = blockIdx.x * 256 + threadIdx.x;   // 32768 threads
    int ks = t >> 8, rem = t & 255, nb = rem >> 5, l = rem & 31;
    int n = nb * 8 + (l >> 2), tig = l & 3;
    int k0 = ks * 16 + 2 * tig, k1 = k0 + 8;
    float w00 = w[(size_t)k0 * EE + n],       w01 = w[(size_t)(k0 + 1) * EE + n];
    float w10 = w[(size_t)k1 * EE + n],       w11 = w[(size_t)(k1 + 1) * EE + n];
    __half h00, l00, h01, l01, h10, l10, h11, l11;
    split_f16(w00, h00, l00); split_f16(w01, h01, l01);
    split_f16(w10, h10, l10); split_f16(w11, h11, l11);
    uint4 v;
    v.x = packh2(h00, h01);
    v.y = packh2(h10, h11);
    v.z = packh2(l00, l01);
    v.w = packh2(l10, l11);
    g_w_frag[t] = v;
    if (we && t < EE) out[ACT_OFF + t] = 0.0f;
}

// ======================= main kernel: no smem mainloop, no barriers =======================
__global__ __launch_bounds__(NT, 1)
void router_mma_kernel(const float* __restrict__ x,
                       const float* __restrict__ noise,
                       float* __restrict__ out,
                       int write_extras) {
    extern __shared__ uint32_t smu[];
    const int tid = threadIdx.x;
    const int wid = tid >> 5;
    const int lid = tid & 31;
    const int s   = wid & 1;           // K half: 0 -> k<1024, 1 -> k>=1024
    const int rb  = (wid >> 1) * 16;   // row block (16 rows per warp)
    const int g   = lid >> 2;
    const int tig = lid & 3;
    const int row0 = blockIdx.x * BM;

    // x base pointers for this thread's two fragment rows
    const float* xr0 = x + (size_t)(row0 + rb + g) * DD + s * 1024 + 2 * tig;
    const float* xr8 = xr0 + 8 * (size_t)DD;
    // B fragment stream for this lane
    const uint4* Bg = g_w_frag + lid;
    const int bbase = s * 64 * 8;      // k16-step base * 8 nb

    float acc[8][4];
#pragma unroll
    for (int nb = 0; nb < 8; nb++)
#pragma unroll
        for (int i = 0; i < 4; i++) acc[nb][i] = 0.0f;

    // A reg double-buffer: av[ks*4 + {r0k0, r0k8, r8k0, r8k8}]
    float2 av[8], avn[8];
#pragma unroll
    for (int ks = 0; ks < 2; ks++) {
        av[ks * 4 + 0] = *(const float2*)(xr0 + ks * 16);
        av[ks * 4 + 1] = *(const float2*)(xr0 + ks * 16 + 8);
        av[ks * 4 + 2] = *(const float2*)(xr8 + ks * 16);
        av[ks * 4 + 3] = *(const float2*)(xr8 + ks * 16 + 8);
    }

#pragma unroll 2
    for (int c = 0; c < NCH; ++c) {
        // prefetch next chunk's A (harmless reload on last iter)
        const int cn = (c + 1 < NCH) ? c + 1 : c;
#pragma unroll
        for (int ks = 0; ks < 2; ks++) {
            avn[ks * 4 + 0] = *(const float2*)(xr0 + cn * 32 + ks * 16);
            avn[ks * 4 + 1] = *(const float2*)(xr0 + cn * 32 + ks * 16 + 8);
            avn[ks * 4 + 2] = *(const float2*)(xr8 + cn * 32 + ks * 16);
            avn[ks * 4 + 3] = *(const float2*)(xr8 + cn * 32 + ks * 16 + 8);
        }

#pragma unroll
        for (int ks = 0; ks < 2; ks++) {
            // B fragments from L2 (fragment-major, coalesced LDG.128)
            uint4 bv[8];
            const int kstep = bbase + (c * 2 + ks) * 8;
#pragma unroll
            for (int nb = 0; nb < 8; nb++) bv[nb] = Bg[(kstep + nb) * 32];

            // convert A fragments (covers part of the B L2 latency)
            uint32_t ah[4], al[4];
            ah[0] = split2(av[ks * 4 + 0], al[0]);
            ah[1] = split2(av[ks * 4 + 2], al[1]);
            ah[2] = split2(av[ks * 4 + 1], al[2]);
            ah[3] = split2(av[ks * 4 + 3], al[3]);

            // pass-major: accumulator reuse distance = 8 (no RAW chains)
#pragma unroll
            for (int nb = 0; nb < 8; nb++) mma_f16(acc[nb], ah, bv[nb].x, bv[nb].y);  // h*h
#pragma unroll
            for (int nb = 0; nb < 8; nb++) mma_f16(acc[nb], ah, bv[nb].z, bv[nb].w);  // h*l
#pragma unroll
            for (int nb = 0; nb < 8; nb++) mma_f16(acc[nb], al, bv[nb].x, bv[nb].y);  // l*h
        }
#pragma unroll
        for (int i = 0; i < 8; i++) av[i] = avn[i];
    }

    // ================= epilogue =================
    float* sc0 = (float*)smu;              // board half 0: [128][66]
    float* sc1 = (float*)(smu + BOARD_U32);
    int*   counts = (int*)(smu + CNT);
    int*   i1a = (int*)(smu + I1A);
    int*   i2a = (int*)(smu + I2A);
    float* g1a = (float*)(smu + G1A);
    float* g2a = (float*)(smu + G2A);

    // scatter accumulators to this half's board
    {
        float* scb = s ? sc1 : sc0;
        const int r0 = rb + g;
#pragma unroll
        for (int nb = 0; nb < 8; nb++) {
            int cc = nb * 8 + tig * 2;
            float2 v0; v0.x = acc[nb][0]; v0.y = acc[nb][1];
            float2 v1; v1.x = acc[nb][2]; v1.y = acc[nb][3];
            *(float2*)(scb + r0 * SC_STRIDE + cc)       = v0;
            *(float2*)(scb + (r0 + 8) * SC_STRIDE + cc) = v1;
        }
    }
    if (tid < EE) counts[tid] = 0;
    __syncthreads();

    // sum K-halves + noise (coalesced)
#pragma unroll
    for (int j = 0; j < 16; j++) {
        int flat = tid + NT * j;           // 8192 elems
        int r = flat >> 6, e = flat & 63;
        sc0[r * SC_STRIDE + e] = sc0[r * SC_STRIDE + e] + sc1[r * SC_STRIDE + e]
                               + noise[(size_t)row0 * EE + flat];
    }
    __syncthreads();

    // per-row top-2 + gates (renormalized top-2 softmax == sigmoid of score diff)
    if (tid < BM) {
        const int row = tid;
        const float* p = sc0 + row * SC_STRIDE;
        float m1 = -3.402823466e38f, m2 = -3.402823466e38f;
        int b1 = 0, b2 = 0;
#pragma unroll
        for (int e = 0; e < EE; e++) {
            float z = p[e];
            if (z > m1) { m2 = m1; b2 = b1; m1 = z; b1 = e; }
            else if (z > m2) { m2 = z; b2 = e; }
        }
        float e2 = __expf(m2 - m1);
        float inv = 1.0f / (1.0f + e2);
        float g1 = inv, g2 = e2 * inv;
        i1a[row] = b1; i2a[row] = b2; g1a[row] = g1; g2a[row] = g2;
        atomicAdd(&counts[b1], 1);
        atomicAdd(&counts[b2], 1);
        if (write_extras) {
            float2 iv; iv.x = (float)b1; iv.y = (float)b2;
            *(float2*)(out + IDX_OFF + (size_t)(row0 + row) * 2) = iv;
            float2 gv; gv.x = g1; gv.y = g2;
            *(float2*)(out + GATE_OFF + (size_t)(row0 + row) * 2) = gv;
        }
    }
    __syncthreads();

    // combine tensor (float4 coalesced)
#pragma unroll
    for (int j = 0; j < 4; j++) {
        int chunk = tid + NT * j;          // 2048 float4
        int r = chunk >> 4, c4 = chunk & 15;
        int b1 = i1a[r], b2 = i2a[r];
        float G1 = g1a[r], G2 = g2a[r];
        int cc = c4 * 4;
        float4 v;
        v.x = (cc     == b1) ? G1 : ((cc     == b2) ? G2 : 0.0f);
        v.y = (cc + 1 == b1) ? G1 : ((cc + 1 == b2) ? G2 : 0.0f);
        v.z = (cc + 2 == b1) ? G1 : ((cc + 2 == b2) ? G2 : 0.0f);
        v.w = (cc + 3 == b1) ? G1 : ((cc + 3 == b2) ? G2 : 0.0f);
        *(float4*)(out + (size_t)(row0 + r) * EE + cc) = v;
    }

    if (write_extras && tid < EE) {
        int cnt = counts[tid];
        if (cnt > 0) atomicAdd(out + ACT_OFF + tid, (float)cnt);
    }
}

extern "C" void kernel_launch(void* const* d_in, const int* in_sizes, int n_in,
                              void* d_out, int out_size) {
    const float* x     = (const float*)d_in[0];
    const float* w     = (const float*)d_in[1];
    const float* noise = (const float*)d_in[2];
    float* out = (float*)d_out;

    const int write_extras = ((size_t)out_size >= FULL_OUT) ? 1 : 0;

    cudaFuncSetAttribute(router_mma_kernel,
                         cudaFuncAttributeMaxDynamicSharedMemorySize, SMEM_BYTES);

    prep_kernel<<<128, 256>>>(w, out, write_extras);
    router_mma_kernel<<<TT / BM, NT, SMEM_BYTES>>>(x, noise, out, write_extras);
}